// round 1
// baseline (speedup 1.0000x reference)
#include <cuda_runtime.h>

#define NE 8
#define DD 1024
#define RR 64
#define TT 128
#define KC 32
#define DC 32
#define MAXN 16384
#define SCALING_F 2.0f

// Device scratch (static allocations only — harness forbids cudaMalloc)
__device__ int   g_counts[NE];
__device__ int   g_tok[NE * MAXN];     // encoded tok*2 + k
__device__ float g_gate[NE * MAXN];
__device__ float g_scratch[2u * MAXN * DD];   // 128 MB: per-(token,k) contribution

// ---------------------------------------------------------------------------
// Router: 1 warp per token. logits = x @ Wg^T + bg; top-2; softmax over the 2.
// Compacts (token,k) into per-expert lists via atomic counters.
// ---------------------------------------------------------------------------
__global__ void router_kernel(const float* __restrict__ x,
                              const float* __restrict__ Wg,
                              const float* __restrict__ bg, int N) {
    __shared__ float sWg[NE * DD];   // 32 KB
    int tid = threadIdx.x;
    for (int i = tid; i < NE * DD; i += blockDim.x) sWg[i] = Wg[i];
    __syncthreads();

    int warp = tid >> 5, lane = tid & 31;
    int tok = blockIdx.x * (blockDim.x >> 5) + warp;
    if (tok >= N) return;

    const float* xr = x + (size_t)tok * DD;
    float acc[NE];
#pragma unroll
    for (int e = 0; e < NE; e++) acc[e] = 0.f;

    for (int i = lane; i < DD; i += 32) {
        float xv = xr[i];
#pragma unroll
        for (int e = 0; e < NE; e++) acc[e] = fmaf(xv, sWg[e * DD + i], acc[e]);
    }
#pragma unroll
    for (int e = 0; e < NE; e++) {
#pragma unroll
        for (int off = 16; off; off >>= 1)
            acc[e] += __shfl_xor_sync(0xffffffffu, acc[e], off);
    }

    if (lane == 0) {
        float l[NE];
#pragma unroll
        for (int e = 0; e < NE; e++) l[e] = acc[e] + bg[e];
        int i0 = 0;
#pragma unroll
        for (int e = 1; e < NE; e++) if (l[e] > l[i0]) i0 = e;
        int i1 = (i0 == 0) ? 1 : 0;
#pragma unroll
        for (int e = 0; e < NE; e++) if (e != i0 && l[e] > l[i1]) i1 = e;

        float ex = expf(l[i1] - l[i0]);           // stable: l[i0] is the max
        float inv = 1.f / (1.f + ex);
        float g0 = inv, g1 = ex * inv;

        int p0 = atomicAdd(&g_counts[i0], 1);
        g_tok[i0 * MAXN + p0]  = tok * 2 + 0;
        g_gate[i0 * MAXN + p0] = g0;
        int p1 = atomicAdd(&g_counts[i1], 1);
        g_tok[i1 * MAXN + p1]  = tok * 2 + 1;
        g_gate[i1 * MAXN + p1] = g1;
    }
}

// ---------------------------------------------------------------------------
// Expert kernel: block = (expert e, tile of up to 128 tokens), 256 threads.
// fc1: H = gelu(X @ W1[e]^T) * gate * SCALING ; fc2: Y = H @ W2[e]^T
// Plain stores into scratch[(tok*2+k)][:] — no atomics.
// ---------------------------------------------------------------------------
__global__ void __launch_bounds__(256, 2)
expert_kernel(const float* __restrict__ x,
              const float* __restrict__ W1,
              const float* __restrict__ W2, int N) {
    __shared__ union {
        struct { float Xs[TT][KC + 1];  float W1s[RR][KC + 1]; } p1;  // 25.3 KB
        struct { float Hs[TT][RR + 5];  float W2s[DC][RR + 1]; } p2;  // 43.6 KB
    } u;
    __shared__ int   s_tok[TT];
    __shared__ float s_gate[TT];

    int e    = blockIdx.x;
    int tile = blockIdx.y;
    int cnt  = g_counts[e];
    int base = tile * TT;
    if (base >= cnt) return;
    int nt = min(TT, cnt - base);

    int t  = threadIdx.x;
    int tx = t & 15;        // 16 column groups
    int ty = t >> 4;        // 16 row groups (8 rows each)

    if (t < TT) {
        if (t < nt) {
            s_tok[t]  = g_tok[e * MAXN + base + t];
            s_gate[t] = g_gate[e * MAXN + base + t];
        } else {
            s_tok[t]  = 0;
            s_gate[t] = 0.f;
        }
    }
    __syncthreads();

    // ---------------- fc1: acc[8][4] over D in chunks of 32 ----------------
    float acc[8][4];
#pragma unroll
    for (int uu = 0; uu < 8; uu++)
#pragma unroll
        for (int vv = 0; vv < 4; vv++) acc[uu][vv] = 0.f;

    const float* W1e = W1 + (size_t)e * RR * DD;

    for (int k0 = 0; k0 < DD; k0 += KC) {
        // stage X tile (gathered rows), zero-padded beyond nt
        for (int idx = t; idx < TT * KC; idx += 256) {
            int row = idx >> 5, kk = idx & 31;
            float v = 0.f;
            if (row < nt) v = x[(size_t)(s_tok[row] >> 1) * DD + k0 + kk];
            u.p1.Xs[row][kk] = v;
        }
        // stage W1 tile
        for (int idx = t; idx < RR * KC; idx += 256) {
            int r = idx >> 5, kk = idx & 31;
            u.p1.W1s[r][kk] = W1e[(size_t)r * DD + k0 + kk];
        }
        __syncthreads();

#pragma unroll
        for (int kk = 0; kk < KC; kk++) {
            float xv[8], wv[4];
#pragma unroll
            for (int uu = 0; uu < 8; uu++) xv[uu] = u.p1.Xs[ty * 8 + uu][kk];
#pragma unroll
            for (int vv = 0; vv < 4; vv++) wv[vv] = u.p1.W1s[tx * 4 + vv][kk];
#pragma unroll
            for (int uu = 0; uu < 8; uu++)
#pragma unroll
                for (int vv = 0; vv < 4; vv++)
                    acc[uu][vv] = fmaf(xv[uu], wv[vv], acc[uu][vv]);
        }
        __syncthreads();
    }

    // gelu(exact erf) with gate*SCALING folded in; write H to smem (reuses P1)
#pragma unroll
    for (int uu = 0; uu < 8; uu++) {
        int row = ty * 8 + uu;
        float gs = s_gate[row] * SCALING_F;
#pragma unroll
        for (int vv = 0; vv < 4; vv++) {
            float v = acc[uu][vv];
            float g = 0.5f * v * (1.f + erff(v * 0.70710678118654752f));
            u.p2.Hs[row][tx * 4 + vv] = g * gs;
        }
    }
    __syncthreads();

    // ---------------- fc2: loop d-chunks of 32 ----------------
    const float* W2e = W2 + (size_t)e * DD * RR;

    for (int d0 = 0; d0 < DD; d0 += DC) {
        for (int idx = t; idx < DC * RR; idx += 256) {
            int dcol = idx >> 6, r = idx & 63;
            u.p2.W2s[dcol][r] = W2e[(size_t)(d0 + dcol) * RR + r];
        }
        __syncthreads();

        float acc2[8][2];
#pragma unroll
        for (int uu = 0; uu < 8; uu++) { acc2[uu][0] = 0.f; acc2[uu][1] = 0.f; }

#pragma unroll 8
        for (int r = 0; r < RR; r++) {
            float w0 = u.p2.W2s[tx * 2 + 0][r];
            float w1 = u.p2.W2s[tx * 2 + 1][r];
#pragma unroll
            for (int uu = 0; uu < 8; uu++) {
                float hv = u.p2.Hs[ty * 8 + uu][r];
                acc2[uu][0] = fmaf(hv, w0, acc2[uu][0]);
                acc2[uu][1] = fmaf(hv, w1, acc2[uu][1]);
            }
        }

#pragma unroll
        for (int uu = 0; uu < 8; uu++) {
            int row = ty * 8 + uu;
            if (row < nt) {
                int slot = s_tok[row];   // tok*2 + k
                float2 val = make_float2(acc2[uu][0], acc2[uu][1]);
                *reinterpret_cast<float2*>(
                    &g_scratch[(size_t)slot * DD + d0 + tx * 2]) = val;
            }
        }
        __syncthreads();
    }
}

// ---------------------------------------------------------------------------
// Combine: out[tok] = scratch[tok,0] + scratch[tok,1]  (float4, write-all)
// ---------------------------------------------------------------------------
__global__ void combine_kernel(float* __restrict__ out, int N) {
    int i = blockIdx.x * blockDim.x + threadIdx.x;
    int total = N * (DD / 4);
    if (i >= total) return;
    int tok = i >> 8;          // DD/4 = 256 float4 per row
    int dd  = i & 255;
    const float4* s = reinterpret_cast<const float4*>(g_scratch);
    float4 a = s[(size_t)tok * 512 + dd];
    float4 b = s[(size_t)tok * 512 + 256 + dd];
    float4 o;
    o.x = a.x + b.x; o.y = a.y + b.y; o.z = a.z + b.z; o.w = a.w + b.w;
    reinterpret_cast<float4*>(out)[i] = o;
}

// ---------------------------------------------------------------------------
extern "C" void kernel_launch(void* const* d_in, const int* in_sizes, int n_in,
                              void* d_out, int out_size) {
    const float* x  = (const float*)d_in[0];
    const float* Wg = (const float*)d_in[1];
    const float* bg = (const float*)d_in[2];
    const float* W1 = (const float*)d_in[3];
    const float* W2 = (const float*)d_in[4];
    float* out = (float*)d_out;
    int N = in_sizes[0] / DD;   // 16384

    void* counts_ptr = nullptr;
    cudaGetSymbolAddress(&counts_ptr, g_counts);
    cudaMemsetAsync(counts_ptr, 0, NE * sizeof(int), 0);

    int rblocks = (N + 7) / 8;                         // 8 warps (tokens)/block
    router_kernel<<<rblocks, 256>>>(x, Wg, bg, N);

    dim3 egrid(NE, (N + TT - 1) / TT);
    expert_kernel<<<egrid, 256>>>(x, W1, W2, N);

    int total = N * (DD / 4);
    combine_kernel<<<(total + 255) / 256, 256>>>(out, N);
}

// round 3
// speedup vs baseline: 2.1885x; 2.1885x over previous
#include <cuda_runtime.h>
#include <cuda_bf16.h>
#include <stdint.h>

#define NE 8
#define DD 1024
#define RR 64
#define TT 128
#define MAXN 16384
#define S1 104          // fc1 smem stride in bf16 (96 data + 8 pad)
#define S2 200          // fc2 smem stride in bf16 (192 data + 8 pad)

// ------------------------- device scratch ----------------------------------
__device__ int   g_counts[NE];
__device__ int   g_tok[NE * MAXN];          // encoded tok*2 + k
__device__ float g_gate[NE * MAXN];
__device__ float g_scratch[2u * MAXN * DD]; // 128 MB per-(token,k) contribution

// ------------------------- helpers -----------------------------------------
__device__ __forceinline__ uint32_t smem_u32(const void* p) {
    uint32_t a;
    asm("{ .reg .u64 t; cvta.to.shared.u64 t, %1; cvt.u32.u64 %0, t; }"
        : "=r"(a) : "l"(p));
    return a;
}
__device__ __forceinline__ void ldsm4(uint32_t* r, uint32_t addr) {
    asm volatile("ldmatrix.sync.aligned.m8n8.x4.shared.b16 {%0,%1,%2,%3}, [%4];"
                 : "=r"(r[0]), "=r"(r[1]), "=r"(r[2]), "=r"(r[3]) : "r"(addr));
}
__device__ __forceinline__ void mma16816(float* c, const uint32_t* a,
                                         const uint32_t* b) {
    asm volatile("mma.sync.aligned.m16n8k16.row.col.f32.bf16.bf16.f32 "
                 "{%0,%1,%2,%3}, {%4,%5,%6,%7}, {%8,%9}, {%0,%1,%2,%3};"
                 : "+f"(c[0]), "+f"(c[1]), "+f"(c[2]), "+f"(c[3])
                 : "r"(a[0]), "r"(a[1]), "r"(a[2]), "r"(a[3]),
                   "r"(b[0]), "r"(b[1]));
}
__device__ __forceinline__ void split2(float v, uint32_t& h, uint32_t& l) {
    __nv_bfloat16 hb = __float2bfloat16(v);
    h = (uint32_t)__bfloat16_as_ushort(hb);
    l = (uint32_t)__bfloat16_as_ushort(__float2bfloat16(v - __bfloat162float(hb)));
}
// A operand triple: per elem (h, l, h)
__device__ __forceinline__ void packA(float4 v, void* dst) {
    uint32_t h0,l0,h1,l1,h2,l2,h3,l3;
    split2(v.x,h0,l0); split2(v.y,h1,l1); split2(v.z,h2,l2); split2(v.w,h3,l3);
    uint2* d = (uint2*)dst;
    d[0] = make_uint2(h0 | (l0 << 16), h0 | (h1 << 16));
    d[1] = make_uint2(l1 | (h1 << 16), h2 | (l2 << 16));
    d[2] = make_uint2(h2 | (h3 << 16), l3 | (h3 << 16));
}
// B operand triple: per elem (h, h, l)
__device__ __forceinline__ void packB(float4 v, void* dst) {
    uint32_t h0,l0,h1,l1,h2,l2,h3,l3;
    split2(v.x,h0,l0); split2(v.y,h1,l1); split2(v.z,h2,l2); split2(v.w,h3,l3);
    uint2* d = (uint2*)dst;
    d[0] = make_uint2(h0 | (h0 << 16), l0 | (h1 << 16));
    d[1] = make_uint2(h1 | (l1 << 16), h2 | (h2 << 16));
    d[2] = make_uint2(l2 | (h3 << 16), h3 | (l3 << 16));
}

// ---------------------------------------------------------------------------
// Router: warp per token (4 tokens sequentially), float4 loads.
// ---------------------------------------------------------------------------
__global__ void router_kernel(const float* __restrict__ x,
                              const float* __restrict__ Wg,
                              const float* __restrict__ bg, int N) {
    __shared__ float4 sWg[NE * 256];
    int t = threadIdx.x;
    const float4* Wg4 = (const float4*)Wg;
    for (int i = t; i < NE * 256; i += 256) sWg[i] = Wg4[i];
    __syncthreads();

    int warp = t >> 5, lane = t & 31;
    for (int it = 0; it < 4; it++) {
        int tok = blockIdx.x * 32 + warp * 4 + it;
        if (tok >= N) break;
        const float4* xr = (const float4*)(x + (size_t)tok * DD);
        float acc[NE];
#pragma unroll
        for (int e = 0; e < NE; e++) acc[e] = 0.f;
#pragma unroll
        for (int i = 0; i < 8; i++) {
            float4 xv = xr[i * 32 + lane];
#pragma unroll
            for (int e = 0; e < NE; e++) {
                float4 w = sWg[e * 256 + i * 32 + lane];
                acc[e] = fmaf(xv.x, w.x, acc[e]);
                acc[e] = fmaf(xv.y, w.y, acc[e]);
                acc[e] = fmaf(xv.z, w.z, acc[e]);
                acc[e] = fmaf(xv.w, w.w, acc[e]);
            }
        }
#pragma unroll
        for (int e = 0; e < NE; e++) {
#pragma unroll
            for (int off = 16; off; off >>= 1)
                acc[e] += __shfl_xor_sync(0xffffffffu, acc[e], off);
        }
        if (lane == 0) {
            float l[NE];
#pragma unroll
            for (int e = 0; e < NE; e++) l[e] = acc[e] + bg[e];
            int i0 = 0;
#pragma unroll
            for (int e = 1; e < NE; e++) if (l[e] > l[i0]) i0 = e;
            int i1 = (i0 == 0) ? 1 : 0;
#pragma unroll
            for (int e = 0; e < NE; e++) if (e != i0 && l[e] > l[i1]) i1 = e;
            float ex = expf(l[i1] - l[i0]);
            float inv = 1.f / (1.f + ex);
            int p0 = atomicAdd(&g_counts[i0], 1);
            g_tok[i0 * MAXN + p0]  = tok * 2;
            g_gate[i0 * MAXN + p0] = inv;
            int p1 = atomicAdd(&g_counts[i1], 1);
            g_tok[i1 * MAXN + p1]  = tok * 2 + 1;
            g_gate[i1 * MAXN + p1] = ex * inv;
        }
    }
}

// ---------------------------------------------------------------------------
// Expert kernel: triple-split bf16 mma.sync GEMMs.
//   fc1: D1[128,64] = X3[128,3072] @ W1_3[64,3072]^T
//   epi: H3 = triplesplit(gelu(D1)*gate*2) -> smem [128, 192]
//   fc2: per 128-col chunk: D2[128,128] = H3 @ W2_3[128,192]^T -> scratch
// smem: bufs region 102400 B (fc1 dbl-buf 2x39936 / fc2 dbl-buf 2x51200),
//       Hs at +102400 (51200 B). Total 153600.
// ---------------------------------------------------------------------------
__global__ void __launch_bounds__(256, 1)
expert_kernel(const float* __restrict__ x,
              const float* __restrict__ W1,
              const float* __restrict__ W2) {
    extern __shared__ char dynsm[];
    __shared__ int   s_tok[TT];
    __shared__ float s_gate[TT];

    int e = blockIdx.x, tile = blockIdx.y;
    int cnt = g_counts[e];
    int base = tile * TT;
    if (base >= cnt) return;
    int nt = min(TT, cnt - base);

    int t = threadIdx.x, wid = t >> 5, l = t & 31;
    int wm = wid & 3, wn = wid >> 2;   // warp grid 4(M) x 2(N)

    if (t < TT) {
        if (t < nt) {
            s_tok[t]  = g_tok[e * MAXN + base + t];
            s_gate[t] = g_gate[e * MAXN + base + t];
        } else {
            s_tok[t]  = g_tok[e * MAXN + base];
            s_gate[t] = 0.f;
        }
    }
    __syncthreads();

    char* bufs = dynsm;
    char* Hs   = dynsm + 102400;
    const float* W1e = W1 + (size_t)e * RR * DD;
    const float* W2e = W2 + (size_t)e * DD * RR;

    // lane-relative ldmatrix offsets (bytes)
    uint32_t a1_lo = (uint32_t)(((l & 7) + ((l >> 3) & 1) * 8) * S1 * 2 + (l >> 4) * 16);
    uint32_t b1_lo = (uint32_t)(((l & 7) + (l >> 4) * 8) * S1 * 2 + ((l >> 3) & 1) * 16);
    uint32_t a2_lo = (uint32_t)(((l & 7) + ((l >> 3) & 1) * 8) * S2 * 2 + (l >> 4) * 16);
    uint32_t b2_lo = (uint32_t)(((l & 7) + (l >> 4) * 8) * S2 * 2 + ((l >> 3) & 1) * 16);
    uint32_t bufs_a = smem_u32(bufs);

    // ================= fc1 =================
    float acc[2][4][4];
#pragma unroll
    for (int i = 0; i < 2; i++)
#pragma unroll
        for (int j = 0; j < 4; j++)
#pragma unroll
            for (int k = 0; k < 4; k++) acc[i][j][k] = 0.f;

    float4 pa[4], pb[2];
    int arow = t >> 3, acol4 = t & 7;

    auto ldg1 = [&](int c) {
#pragma unroll
        for (int j = 0; j < 4; j++) {
            int r = arow + j * 32;
            int tok = s_tok[r] >> 1;
            pa[j] = *(const float4*)(x + (size_t)tok * DD + c * 32 + acol4 * 4);
        }
#pragma unroll
        for (int j = 0; j < 2; j++) {
            int idx = t + j * 256;
            int r = idx >> 3, c4 = idx & 7;
            pb[j] = *(const float4*)(W1e + (size_t)r * DD + c * 32 + c4 * 4);
        }
    };
    auto sts1 = [&](int buf) {
        char* As = bufs + buf * 39936;
        char* Bs = As + 26624;
#pragma unroll
        for (int j = 0; j < 4; j++) {
            int r = arow + j * 32;
            packA(pa[j], As + r * S1 * 2 + acol4 * 24);
        }
#pragma unroll
        for (int j = 0; j < 2; j++) {
            int idx = t + j * 256;
            int r = idx >> 3, c4 = idx & 7;
            packB(pb[j], Bs + r * S1 * 2 + c4 * 24);
        }
    };

    ldg1(0); sts1(0);
    __syncthreads();

    for (int c = 0; c < 32; c++) {
        int buf = c & 1;
        if (c + 1 < 32) ldg1(c + 1);
        uint32_t Aaddr = bufs_a + buf * 39936;
        uint32_t Baddr = Aaddr + 26624;
#pragma unroll
        for (int kk = 0; kk < 6; kk++) {
            uint32_t a[2][4], b[2][4];
#pragma unroll
            for (int mt = 0; mt < 2; mt++)
                ldsm4(a[mt], Aaddr + (wm * 32 + mt * 16) * S1 * 2 + kk * 32 + a1_lo);
#pragma unroll
            for (int pr = 0; pr < 2; pr++)
                ldsm4(b[pr], Baddr + (wn * 32 + pr * 16) * S1 * 2 + kk * 32 + b1_lo);
#pragma unroll
            for (int mt = 0; mt < 2; mt++)
#pragma unroll
                for (int ntl = 0; ntl < 4; ntl++)
                    mma16816(acc[mt][ntl], a[mt], &b[ntl >> 1][(ntl & 1) * 2]);
        }
        if (c + 1 < 32) sts1((c + 1) & 1);
        __syncthreads();
    }

    // ============ epilogue: gelu*gate*2 -> triple-split H in smem ===========
#pragma unroll
    for (int mt = 0; mt < 2; mt++) {
#pragma unroll
        for (int ntl = 0; ntl < 4; ntl++) {
#pragma unroll
            for (int half = 0; half < 2; half++) {
                int r = wm * 32 + mt * 16 + half * 8 + (l >> 2);
                float gs = s_gate[r] * 2.0f;   // SCALING = 128/64
                float v0 = acc[mt][ntl][half * 2 + 0];
                float v1 = acc[mt][ntl][half * 2 + 1];
                float g0 = 0.5f * v0 * (1.f + erff(v0 * 0.70710678118654752f)) * gs;
                float g1 = 0.5f * v1 * (1.f + erff(v1 * 0.70710678118654752f)) * gs;
                int n = wn * 32 + ntl * 8 + (l & 3) * 2;
                uint32_t h0, l0, h1, l1;
                split2(g0, h0, l0); split2(g1, h1, l1);
                uint32_t* d = (uint32_t*)(Hs + r * S2 * 2 + n * 6);
                d[0] = h0 | (l0 << 16);
                d[1] = h0 | (h1 << 16);
                d[2] = l1 | (h1 << 16);
            }
        }
    }
    __syncthreads();

    // ================= fc2 =================
    uint32_t HsA = smem_u32(Hs);
    float4 pw[8];
    auto ldg2 = [&](int nch) {
#pragma unroll
        for (int j = 0; j < 8; j++) {
            int idx = t + j * 256;
            int r = idx >> 4, c4 = idx & 15;
            pw[j] = *(const float4*)(W2e + (size_t)(nch * TT + r) * RR + c4 * 4);
        }
    };
    auto sts2 = [&](int buf) {
        char* Ws = bufs + buf * 51200;
#pragma unroll
        for (int j = 0; j < 8; j++) {
            int idx = t + j * 256;
            int r = idx >> 4, c4 = idx & 15;
            packB(pw[j], Ws + r * S2 * 2 + c4 * 24);
        }
    };

    ldg2(0); sts2(0);
    __syncthreads();

    for (int n = 0; n < 8; n++) {
        int buf = n & 1;
        if (n + 1 < 8) ldg2(n + 1);
        float acc2[2][8][4];
#pragma unroll
        for (int i = 0; i < 2; i++)
#pragma unroll
            for (int j = 0; j < 8; j++)
#pragma unroll
                for (int k = 0; k < 4; k++) acc2[i][j][k] = 0.f;

        uint32_t Waddr = bufs_a + buf * 51200;
#pragma unroll
        for (int kk = 0; kk < 12; kk++) {
            uint32_t a[2][4], b[4][4];
#pragma unroll
            for (int mt = 0; mt < 2; mt++)
                ldsm4(a[mt], HsA + (wm * 32 + mt * 16) * S2 * 2 + kk * 32 + a2_lo);
#pragma unroll
            for (int pr = 0; pr < 4; pr++)
                ldsm4(b[pr], Waddr + (wn * 64 + pr * 16) * S2 * 2 + kk * 32 + b2_lo);
#pragma unroll
            for (int mt = 0; mt < 2; mt++)
#pragma unroll
                for (int ntl = 0; ntl < 8; ntl++)
                    mma16816(acc2[mt][ntl], a[mt], &b[ntl >> 1][(ntl & 1) * 2]);
        }
        // store to scratch
#pragma unroll
        for (int mt = 0; mt < 2; mt++) {
#pragma unroll
            for (int half = 0; half < 2; half++) {
                int r = wm * 32 + mt * 16 + half * 8 + (l >> 2);
                if (r < nt) {
                    int slot = s_tok[r];
                    float* dst = g_scratch + (size_t)slot * DD + n * 128
                               + wn * 64 + (l & 3) * 2;
#pragma unroll
                    for (int ntl = 0; ntl < 8; ntl++)
                        *(float2*)(dst + ntl * 8) =
                            make_float2(acc2[mt][ntl][half * 2 + 0],
                                        acc2[mt][ntl][half * 2 + 1]);
                }
            }
        }
        if (n + 1 < 8) sts2((n + 1) & 1);
        __syncthreads();
    }
}

// ---------------------------------------------------------------------------
__global__ void combine_kernel(float* __restrict__ out, int N) {
    int i = blockIdx.x * blockDim.x + threadIdx.x;
    int total = N * (DD / 4);
    if (i >= total) return;
    int tok = i >> 8;
    int dd  = i & 255;
    const float4* s = (const float4*)g_scratch;
    float4 a = s[(size_t)tok * 512 + dd];
    float4 b = s[(size_t)tok * 512 + 256 + dd];
    float4 o;
    o.x = a.x + b.x; o.y = a.y + b.y; o.z = a.z + b.z; o.w = a.w + b.w;
    ((float4*)out)[i] = o;
}

// ---------------------------------------------------------------------------
extern "C" void kernel_launch(void* const* d_in, const int* in_sizes, int n_in,
                              void* d_out, int out_size) {
    const float* x  = (const float*)d_in[0];
    const float* Wg = (const float*)d_in[1];
    const float* bg = (const float*)d_in[2];
    const float* W1 = (const float*)d_in[3];
    const float* W2 = (const float*)d_in[4];
    float* out = (float*)d_out;
    int N = in_sizes[0] / DD;

    cudaFuncSetAttribute(expert_kernel,
                         cudaFuncAttributeMaxDynamicSharedMemorySize, 153600);

    void* counts_ptr = nullptr;
    cudaGetSymbolAddress(&counts_ptr, g_counts);
    cudaMemsetAsync(counts_ptr, 0, NE * sizeof(int), 0);

    router_kernel<<<(N + 31) / 32, 256>>>(x, Wg, bg, N);

    dim3 egrid(NE, 128);
    expert_kernel<<<egrid, 256, 153600>>>(x, W1, W2);

    int total = N * (DD / 4);
    combine_kernel<<<(total + 255) / 256, 256>>>(out, N);
}